// round 1
// baseline (speedup 1.0000x reference)
#include <cuda_runtime.h>
#include <cuda_fp16.h>
#include <cstdint>

// ---------------------------------------------------------------------------
// MoE (AriaExperts): top-2 routing + grouped fp16 GEMM (SwiGLU fused) + combine
// Shapes: tokens=2048, hidden=1024, inter=2048, experts=8, topk=2
// ---------------------------------------------------------------------------

#define NT     2048
#define HID    1024
#define INTERD 2048
#define NE     8
#define TK     2
#define NP     (NT*TK)      // 4096 pairs
#define NPP    (NP + 128)   // padded rows (tiles may overrun expert segment)

// ---- device scratch (allocation-free rule: __device__ globals) ----
__device__ __align__(16) __half g_Xp [NPP * HID];     // permuted tokens, fp16
__device__ __align__(16) __half g_Act[NPP * INTERD];  // SwiGLU activations, fp16
__device__ int   g_pair_token[NPP];
__device__ float g_pair_score[NPP];
__device__ int   g_counts[NE];
__device__ int   g_fill[NE];
__device__ int   g_offsets[NE + 1];
__device__ int   g_tok_e[NT * TK];
__device__ float g_tok_s[NT * TK];

// ---------------------------------------------------------------------------
// 1) zero output + counters
// ---------------------------------------------------------------------------
__global__ void zero_kernel(float* __restrict__ out) {
    int i = blockIdx.x * blockDim.x + threadIdx.x;
    if (i < NT * HID) out[i] = 0.0f;
    if (i < NE) { g_counts[i] = 0; g_fill[i] = 0; }
}

// ---------------------------------------------------------------------------
// 2) routing: top-2 of 8 logits + softmax over the two selected
// ---------------------------------------------------------------------------
__global__ void route_kernel(const float* __restrict__ logits) {
    int t = blockIdx.x * blockDim.x + threadIdx.x;
    if (t >= NT) return;
    float l[NE];
#pragma unroll
    for (int i = 0; i < NE; i++) l[i] = logits[t * NE + i];
    int b0 = 0; float v0 = l[0];
#pragma unroll
    for (int i = 1; i < NE; i++) if (l[i] > v0) { v0 = l[i]; b0 = i; }
    int b1 = -1; float v1 = -1e30f;
#pragma unroll
    for (int i = 0; i < NE; i++) if (i != b0 && l[i] > v1) { v1 = l[i]; b1 = i; }
    float e1  = __expf(v1 - v0);
    float inv = 1.0f / (1.0f + e1);
    g_tok_e[t * 2 + 0] = b0; g_tok_s[t * 2 + 0] = inv;
    g_tok_e[t * 2 + 1] = b1; g_tok_s[t * 2 + 1] = e1 * inv;
    atomicAdd(&g_counts[b0], 1);
    atomicAdd(&g_counts[b1], 1);
}

// ---------------------------------------------------------------------------
// 3) exclusive prefix over 8 expert counts
// ---------------------------------------------------------------------------
__global__ void offsets_kernel() {
    if (threadIdx.x == 0) {
        int s = 0;
#pragma unroll
        for (int e = 0; e < NE; e++) { g_offsets[e] = s; s += g_counts[e]; }
        g_offsets[NE] = s;
    }
}

// ---------------------------------------------------------------------------
// 4) scatter token-expert pairs into expert-grouped order
// ---------------------------------------------------------------------------
__global__ void scatter_kernel() {
    int t = blockIdx.x * blockDim.x + threadIdx.x;
    if (t >= NT) return;
#pragma unroll
    for (int k = 0; k < TK; k++) {
        int e = g_tok_e[t * 2 + k];
        int pos = g_offsets[e] + atomicAdd(&g_fill[e], 1);
        g_pair_token[pos] = t;
        g_pair_score[pos] = g_tok_s[t * 2 + k];
    }
}

// ---------------------------------------------------------------------------
// 5) gather + fp32->fp16 convert permuted token rows
// ---------------------------------------------------------------------------
__global__ void permute_kernel(const float* __restrict__ X) {
    int r = blockIdx.x;              // pair row, 0..NP-1
    int t = g_pair_token[r];
    int c = threadIdx.x * 8;         // 128 threads * 8 = 1024
    const float4* s = (const float4*)(X + (size_t)t * HID + c);
    float4 v0 = s[0], v1 = s[1];
    union { __half h[8]; uint4 u; } cv;
    cv.h[0] = __float2half_rn(v0.x); cv.h[1] = __float2half_rn(v0.y);
    cv.h[2] = __float2half_rn(v0.z); cv.h[3] = __float2half_rn(v0.w);
    cv.h[4] = __float2half_rn(v1.x); cv.h[5] = __float2half_rn(v1.y);
    cv.h[6] = __float2half_rn(v1.z); cv.h[7] = __float2half_rn(v1.w);
    *(uint4*)(g_Xp + (size_t)r * HID + c) = cv.u;
}

// ---------------------------------------------------------------------------
// Grouped GEMM, double-buffered smem, mma.sync m16n8k16 f16->f32.
// MODE 0: FC1 fused SwiGLU.  A = g_Xp [pairs,1024], W = w1[e][1024][4096]
//         block tile: 128 rows x 64 act cols (B tile = 64 proj + 64 gate cols)
// MODE 1: FC2.               A = g_Act [pairs,2048], W = w2[e][2048][1024]
//         epilogue: score-weighted atomicAdd into out[token][col]
// ---------------------------------------------------------------------------
#define MMA_OP(ACC, AF, B0, B1)                                               \
    asm volatile("mma.sync.aligned.m16n8k16.row.col.f32.f16.f16.f32 "         \
        "{%0,%1,%2,%3}, {%4,%5,%6,%7}, {%8,%9}, {%0,%1,%2,%3};"               \
        : "+f"(ACC[0]), "+f"(ACC[1]), "+f"(ACC[2]), "+f"(ACC[3])              \
        : "r"(AF[0]), "r"(AF[1]), "r"(AF[2]), "r"(AF[3]), "r"(B0), "r"(B1))

template <int MODE>
__global__ __launch_bounds__(256)
void moe_gemm_kernel(const float* __restrict__ W, float* __restrict__ outp) {
    constexpr int BM  = 128, BK = 32;
    constexpr int K   = (MODE == 0) ? HID : INTERD;
    constexpr int LDA = K;
    constexpr int LDB = (MODE == 0) ? (2 * INTERD) : HID;
    constexpr int KT  = K / BK;

    const int e   = blockIdx.z;
    const int cnt = g_counts[e];
    const int mt  = blockIdx.y;
    if (mt * BM >= cnt) return;
    const int bn      = blockIdx.x;
    const int exp_off = g_offsets[e];
    const int rowbase = exp_off + mt * BM;
    const int rowlim  = exp_off + cnt;

    const __half* __restrict__ Ag = (MODE == 0) ? g_Xp : g_Act;
    const float*  __restrict__ Wg = W + (size_t)e * K * LDB;

    __shared__ __align__(16) __half As[2][BM][BK + 8];
    __shared__ __align__(16) __half Bs[2][BK][128 + 8];

    const int tid  = threadIdx.x;
    const int lane = tid & 31;
    const int wid  = tid >> 5;
    const int wm   = wid & 3;   // 4 warps along M (32 rows each)
    const int wn   = wid >> 2;  // 2 warps along N

    // per-thread load coordinates
    int a_row[2], a_col[2];
#pragma unroll
    for (int i = 0; i < 2; i++) { int u = i * 256 + tid; a_row[i] = u >> 2; a_col[i] = (u & 3) * 8; }
    int b_row[4], b_sc[4], b_dc[4];
#pragma unroll
    for (int i = 0; i < 4; i++) {
        int f = i * 256 + tid; int r = f >> 5; int cs = f & 31;
        b_row[i] = r; b_dc[i] = cs * 4;
        if (MODE == 0)
            b_sc[i] = (cs < 16) ? (bn * 64 + cs * 4) : (INTERD + bn * 64 + (cs - 16) * 4);
        else
            b_sc[i] = bn * 128 + cs * 4;
    }

    float acc[2][8][4];
#pragma unroll
    for (int a = 0; a < 2; a++)
#pragma unroll
        for (int b = 0; b < 8; b++)
#pragma unroll
            for (int c = 0; c < 4; c++) acc[a][b][c] = 0.0f;

    // prologue: tile 0 -> smem[0]
#pragma unroll
    for (int i = 0; i < 2; i++)
        *(uint4*)&As[0][a_row[i]][a_col[i]] =
            *(const uint4*)(Ag + (size_t)(rowbase + a_row[i]) * LDA + a_col[i]);
#pragma unroll
    for (int i = 0; i < 4; i++) {
        float4 v = *(const float4*)(Wg + (size_t)b_row[i] * LDB + b_sc[i]);
        union { __half h[4]; uint2 u; } cv;
        cv.h[0] = __float2half_rn(v.x); cv.h[1] = __float2half_rn(v.y);
        cv.h[2] = __float2half_rn(v.z); cv.h[3] = __float2half_rn(v.w);
        *(uint2*)&Bs[0][b_row[i]][b_dc[i]] = cv.u;
    }
    __syncthreads();

    for (int kt = 0; kt < KT; kt++) {
        const int cur = kt & 1;
        uint4 aR[2]; float4 bR[4];
        const bool pf = (kt + 1 < KT);
        if (pf) {
            const int k0 = (kt + 1) * BK;
#pragma unroll
            for (int i = 0; i < 2; i++)
                aR[i] = *(const uint4*)(Ag + (size_t)(rowbase + a_row[i]) * LDA + k0 + a_col[i]);
#pragma unroll
            for (int i = 0; i < 4; i++)
                bR[i] = *(const float4*)(Wg + (size_t)(k0 + b_row[i]) * LDB + b_sc[i]);
        }
#pragma unroll
        for (int ks = 0; ks < BK; ks += 16) {
            uint32_t af[2][4];
#pragma unroll
            for (int mf = 0; mf < 2; mf++) {
                const __half* p = &As[cur][wm * 32 + mf * 16 + (lane & 15)][ks + (lane >> 4) * 8];
                uint32_t sp = (uint32_t)__cvta_generic_to_shared(p);
                asm volatile("ldmatrix.sync.aligned.m8n8.x4.shared.b16 {%0,%1,%2,%3}, [%4];"
                    : "=r"(af[mf][0]), "=r"(af[mf][1]), "=r"(af[mf][2]), "=r"(af[mf][3]) : "r"(sp));
            }
            uint32_t bf[4][4];
#pragma unroll
            for (int g = 0; g < 4; g++) {
                int bcol = (MODE == 0)
                    ? ((g < 2) ? (wn * 32 + g * 16) : (64 + wn * 32 + (g - 2) * 16))
                    : (wn * 64 + g * 16);
                const __half* p = &Bs[cur][ks + (lane & 15)][bcol + (lane >> 4) * 8];
                uint32_t sp = (uint32_t)__cvta_generic_to_shared(p);
                asm volatile("ldmatrix.sync.aligned.m8n8.x4.trans.shared.b16 {%0,%1,%2,%3}, [%4];"
                    : "=r"(bf[g][0]), "=r"(bf[g][1]), "=r"(bf[g][2]), "=r"(bf[g][3]) : "r"(sp));
            }
#pragma unroll
            for (int mf = 0; mf < 2; mf++) {
#pragma unroll
                for (int g = 0; g < 4; g++) {
                    MMA_OP(acc[mf][2 * g],     af[mf], bf[g][0], bf[g][1]);
                    MMA_OP(acc[mf][2 * g + 1], af[mf], bf[g][2], bf[g][3]);
                }
            }
        }
        if (pf) {
#pragma unroll
            for (int i = 0; i < 2; i++)
                *(uint4*)&As[cur ^ 1][a_row[i]][a_col[i]] = aR[i];
#pragma unroll
            for (int i = 0; i < 4; i++) {
                union { __half h[4]; uint2 u; } cv;
                cv.h[0] = __float2half_rn(bR[i].x); cv.h[1] = __float2half_rn(bR[i].y);
                cv.h[2] = __float2half_rn(bR[i].z); cv.h[3] = __float2half_rn(bR[i].w);
                *(uint2*)&Bs[cur ^ 1][b_row[i]][b_dc[i]] = cv.u;
            }
        }
        __syncthreads();
    }

    // ---- epilogue ----
    if (MODE == 0) {
        // SwiGLU: acc[.][0..3] = proj, acc[.][4..7] = matching gate cols
#pragma unroll
        for (int mf = 0; mf < 2; mf++) {
            int rb = rowbase + wm * 32 + mf * 16 + (lane >> 2);
#pragma unroll
            for (int h = 0; h < 2; h++) {
                int row = rb + h * 8;
                if (row < rowlim) {
#pragma unroll
                    for (int j = 0; j < 4; j++) {
                        float p0 = acc[mf][j][2 * h],     p1 = acc[mf][j][2 * h + 1];
                        float g0 = acc[mf][j + 4][2 * h], g1 = acc[mf][j + 4][2 * h + 1];
                        float a0 = p0 / (1.0f + __expf(-p0)) * g0;
                        float a1 = p1 / (1.0f + __expf(-p1)) * g1;
                        int col = bn * 64 + wn * 32 + j * 8 + (lane & 3) * 2;
                        *(__half2*)(g_Act + (size_t)row * INTERD + col) = __floats2half2_rn(a0, a1);
                    }
                }
            }
        }
    } else {
#pragma unroll
        for (int mf = 0; mf < 2; mf++) {
            int rb = rowbase + wm * 32 + mf * 16 + (lane >> 2);
#pragma unroll
            for (int h = 0; h < 2; h++) {
                int row = rb + h * 8;
                if (row < rowlim) {
                    int   tkn = g_pair_token[row];
                    float sc  = g_pair_score[row];
                    float* orow = outp + (size_t)tkn * HID;
#pragma unroll
                    for (int nf = 0; nf < 8; nf++) {
                        int col = bn * 128 + wn * 64 + nf * 8 + (lane & 3) * 2;
                        atomicAdd(&orow[col],     acc[mf][nf][2 * h] * sc);
                        atomicAdd(&orow[col + 1], acc[mf][nf][2 * h + 1] * sc);
                    }
                }
            }
        }
    }
}

// ---------------------------------------------------------------------------
extern "C" void kernel_launch(void* const* d_in, const int* in_sizes, int n_in,
                              void* d_out, int out_size) {
    const float* X      = (const float*)d_in[0];  // [2048,1024]
    const float* logits = (const float*)d_in[1];  // [2048,8]
    const float* w1     = (const float*)d_in[2];  // [8,1024,4096]
    const float* w2     = (const float*)d_in[3];  // [8,2048,1024]
    float* out          = (float*)d_out;          // [2048,1024]

    zero_kernel<<<(NT * HID + 255) / 256, 256>>>(out);
    route_kernel<<<(NT + 255) / 256, 256>>>(logits);
    offsets_kernel<<<1, 32>>>();
    scatter_kernel<<<(NT + 255) / 256, 256>>>();
    permute_kernel<<<NP, 128>>>(X);

    // FC1 (+SwiGLU): act cols tiled by 64 -> 32 n-tiles; worst-case 32 m-tiles
    moe_gemm_kernel<0><<<dim3(32, 32, NE), 256>>>(w1, nullptr);
    // FC2: out cols tiled by 128 -> 8 n-tiles
    moe_gemm_kernel<1><<<dim3(8, 32, NE), 256>>>(w2, out);
}